// round 7
// baseline (speedup 1.0000x reference)
#include <cuda_runtime.h>
#include <cuda_fp16.h>
#include <math.h>
#include <stdint.h>

// Shapes fixed by the problem: N=8192, D=512, 3 classes
#define NMAX 8192
#define DMAX 512

// ---------------- device scratch (static, no runtime allocation) ------------
__device__ __half g_fh[(size_t)NMAX * DMAX];   // permuted normalized features (8 MB)
__device__ __half g_S[(size_t)NMAX * NMAX];    // scaled logits, fp16 (class tiles only)
__device__ float  g_negpart[(size_t)NMAX * 64];// per-(row, col-tile) exp partials (2 MB)
__device__ int    g_perm[NMAX];                // sorted order: class0,1,2 valid, invalid
__device__ int    g_bnd[4];                    // {0, b1, b2, NV}
__device__ float  g_rowloss[NMAX];
__device__ int    g_rowflag[NMAX];
__device__ int    g_ctr = 0;                   // completion counter (reset by last block)

// ---------------- helpers ----------------------------------------------------
__device__ __forceinline__ float wred_f(float x) {
#pragma unroll
    for (int o = 16; o; o >>= 1) x += __shfl_xor_sync(0xffffffffu, x, o);
    return x;
}
__device__ __forceinline__ int wred_i(int x) {
#pragma unroll
    for (int o = 16; o; o >>= 1) x += __shfl_xor_sync(0xffffffffu, x, o);
    return x;
}

// exact softplus via fast MUFU paths: log1p(exp(d)) = max(d,0) + log(1+exp(-|d|))
__device__ __forceinline__ float softplus_fast(float d) {
    return fmaxf(d, 0.f) + __logf(1.f + __expf(-fabsf(d)));
}

__device__ __forceinline__ void mma_f16(float* d, const uint32_t* a, const uint32_t* b) {
    asm volatile(
        "mma.sync.aligned.m16n8k16.row.col.f32.f16.f16.f32 "
        "{%0,%1,%2,%3}, {%4,%5,%6,%7}, {%8,%9}, {%0,%1,%2,%3};"
        : "+f"(d[0]), "+f"(d[1]), "+f"(d[2]), "+f"(d[3])
        : "r"(a[0]), "r"(a[1]), "r"(a[2]), "r"(a[3]),
          "r"(b[0]), "r"(b[1]));
}

// ---------------- kernel 0: stable counting sort (1 block, warp scans) ------
__global__ void __launch_bounds__(1024) k_perm(
    const int* __restrict__ labels,
    const int* __restrict__ bad,
    int N)
{
    __shared__ uint32_t wt01[32], wt23[32];
    const int t = threadIdx.x;
    const int lane = t & 31;
    const int wid = t >> 5;

    // 8 contiguous elements per thread via int4 loads
    const int4* lab4 = reinterpret_cast<const int4*>(labels);
    const int4* bad4 = reinterpret_cast<const int4*>(bad);
    int4 l0 = lab4[t * 2], l1 = lab4[t * 2 + 1];
    int4 d0 = bad4[t * 2], d1 = bad4[t * 2 + 1];

    int code[8];
    code[0] = (d0.x == 0) ? l0.x : 3;
    code[1] = (d0.y == 0) ? l0.y : 3;
    code[2] = (d0.z == 0) ? l0.z : 3;
    code[3] = (d0.w == 0) ? l0.w : 3;
    code[4] = (d1.x == 0) ? l1.x : 3;
    code[5] = (d1.y == 0) ? l1.y : 3;
    code[6] = (d1.z == 0) ? l1.z : 3;
    code[7] = (d1.w == 0) ? l1.w : 3;

    int cnt[4] = {0, 0, 0, 0};
#pragma unroll
    for (int e = 0; e < 8; e++) cnt[code[e]]++;

    uint32_t v01 = (uint32_t)cnt[0] | ((uint32_t)cnt[1] << 16);
    uint32_t v23 = (uint32_t)cnt[2] | ((uint32_t)cnt[3] << 16);
    uint32_t s01 = v01, s23 = v23;
#pragma unroll
    for (int off = 1; off < 32; off <<= 1) {
        uint32_t t1 = __shfl_up_sync(0xffffffffu, s01, off);
        uint32_t t2 = __shfl_up_sync(0xffffffffu, s23, off);
        if (lane >= off) { s01 += t1; s23 += t2; }
    }
    if (lane == 31) { wt01[wid] = s01; wt23[wid] = s23; }
    __syncthreads();
    if (wid == 0) {
        uint32_t w1 = wt01[lane], w2 = wt23[lane];
#pragma unroll
        for (int off = 1; off < 32; off <<= 1) {
            uint32_t t1 = __shfl_up_sync(0xffffffffu, w1, off);
            uint32_t t2 = __shfl_up_sync(0xffffffffu, w2, off);
            if (lane >= off) { w1 += t1; w2 += t2; }
        }
        wt01[lane] = w1; wt23[lane] = w2;
    }
    __syncthreads();

    const uint32_t wp01 = wid ? wt01[wid - 1] : 0u;
    const uint32_t wp23 = wid ? wt23[wid - 1] : 0u;
    const uint32_t tt01 = wt01[31], tt23 = wt23[31];

    const uint32_t ep01 = wp01 + s01 - v01;
    const uint32_t ep23 = wp23 + s23 - v23;
    int pre[4] = { (int)(ep01 & 0xffffu), (int)(ep01 >> 16),
                   (int)(ep23 & 0xffffu), (int)(ep23 >> 16) };
    const int tot0 = (int)(tt01 & 0xffffu);
    const int tot1 = (int)(tt01 >> 16);
    const int tot2 = (int)(tt23 & 0xffffu);
    int base[4] = { 0, tot0, tot0 + tot1, tot0 + tot1 + tot2 };

    int r[4] = {0, 0, 0, 0};
#pragma unroll
    for (int e = 0; e < 8; e++) {
        const int j = t * 8 + e;
        const int c = code[e];
        g_perm[base[c] + pre[c] + r[c]] = j;
        r[c]++;
    }
    if (t == 0) {
        g_bnd[0] = 0;
        g_bnd[1] = base[1];
        g_bnd[2] = base[2];
        g_bnd[3] = base[3];              // NV
    }
}

// ---------------- kernel 1: normalize + gather-permute -> fp16 --------------
__global__ void __launch_bounds__(128) k_normalize(
    const float* __restrict__ feats, int N, int D)
{
    const int i = blockIdx.x;
    const int tid = threadIdx.x;
    const int src = g_perm[i];
    float4 v = reinterpret_cast<const float4*>(feats + (size_t)src * D)[tid];
    float ss = v.x * v.x + v.y * v.y + v.z * v.z + v.w * v.w;
    ss = wred_f(ss);
    __shared__ float w[4];
    if ((tid & 31) == 0) w[tid >> 5] = ss;
    __syncthreads();
    float rinv = rsqrtf(w[0] + w[1] + w[2] + w[3]);
    uint2 o;
    __half2 h0 = __floats2half2_rn(v.x * rinv, v.y * rinv);
    __half2 h1 = __floats2half2_rn(v.z * rinv, v.w * rinv);
    o.x = *reinterpret_cast<uint32_t*>(&h0);
    o.y = *reinterpret_cast<uint32_t*>(&h1);
    reinterpret_cast<uint2*>(g_fh + (size_t)i * D)[tid] = o;
}

// ---------------- kernel 2: symmetric fp16 GEMM + fused neg-exp partials ----
#define NTILE 64  // N / 128 (max)

__device__ __forceinline__ int clsof(int x, int b1, int b2, int NV) {
    return (x < b1) ? 0 : (x < b2) ? 1 : (x < NV) ? 2 : 3;
}

__global__ void __launch_bounds__(256) k_gemm_f16(int N, int D)
{
    __shared__ __align__(16) unsigned char smem_raw[34816];
    uint32_t* Asm = reinterpret_cast<uint32_t*>(smem_raw);
    uint32_t* Bsm = reinterpret_cast<uint32_t*>(smem_raw + 16384);
    __half*   Tsm = reinterpret_cast<__half*>(smem_raw);
    float*    SRow = reinterpret_cast<float*>(smem_raw);          // [128][4]
    float*    SCol = reinterpret_cast<float*>(smem_raw + 2048);   // [128][2]

    int t = blockIdx.x;
    int by = 0;
    {
        int rem = t;
        while (rem >= NTILE - by) { rem -= NTILE - by; by++; }
        t = rem;
    }
    const int bx = by + t;

    const int b1 = g_bnd[1];
    const int b2 = g_bnd[2];
    const int NV = g_bnd[3];
    const int ntv = (NV + 127) >> 7;
    if (bx >= ntv) return;

    const int row0 = by * 128;
    const int col0 = bx * 128;

    const int tid  = threadIdx.x;
    const int lane = tid & 31;
    const int warp = tid >> 5;
    const int wm   = warp >> 2;
    const int wn   = warp & 3;

    const int lr  = tid >> 3;
    const int lc2 = (tid & 7) << 2;

    const int D2 = D >> 1;
    const uint32_t* __restrict__ fh2 = reinterpret_cast<const uint32_t*>(g_fh);

    float acc[4][4][4];
#pragma unroll
    for (int a = 0; a < 4; a++)
#pragma unroll
        for (int b = 0; b < 4; b++)
#pragma unroll
            for (int c = 0; c < 4; c++) acc[a][b][c] = 0.f;

    uint4 a4[4], b4[4];
#pragma unroll
    for (int r = 0; r < 4; r++) {
        a4[r] = *reinterpret_cast<const uint4*>(fh2 + (size_t)(row0 + lr + 32 * r) * D2 + lc2);
        b4[r] = *reinterpret_cast<const uint4*>(fh2 + (size_t)(col0 + lr + 32 * r) * D2 + lc2);
    }

    for (int k0 = 0; k0 < D2; k0 += 32) {
        __syncthreads();
#pragma unroll
        for (int r = 0; r < 4; r++) {
            const uint32_t av[4] = {a4[r].x, a4[r].y, a4[r].z, a4[r].w};
            const uint32_t bv[4] = {b4[r].x, b4[r].y, b4[r].z, b4[r].w};
            const int m  = lr + 32 * r;
            const int mt = m >> 4, rr = m & 15;
            const int nt = m >> 3, cc = m & 7;
#pragma unroll
            for (int c = 0; c < 4; c++) {
                const int kc = lc2 + c;
                const int ks = kc >> 3, k7 = kc & 7;
                const int swz = 5 * ks;
                const int laneA = ((((rr & 7) << 2) | (k7 & 3)) ^ swz);
                const int regA  = (rr >> 3) | ((k7 >> 2) << 1);
                Asm[(((ks << 3) + mt) << 7) + (laneA << 2) + regA] = av[c];
                const int laneB = (((cc << 2) | (k7 & 3)) ^ swz);
                const int regB  = k7 >> 2;
                Bsm[(((ks << 4) + nt) << 6) + (laneB << 1) + regB] = bv[c];
            }
        }
        __syncthreads();

        if (k0 + 32 < D2) {
#pragma unroll
            for (int r = 0; r < 4; r++) {
                a4[r] = *reinterpret_cast<const uint4*>(fh2 + (size_t)(row0 + lr + 32 * r) * D2 + lc2 + k0 + 32);
                b4[r] = *reinterpret_cast<const uint4*>(fh2 + (size_t)(col0 + lr + 32 * r) * D2 + lc2 + k0 + 32);
            }
        }

#pragma unroll
        for (int ks = 0; ks < 4; ks++) {
            const int lsw = lane ^ (5 * ks);
            uint32_t A[4][4];
#pragma unroll
            for (int mt_ = 0; mt_ < 4; mt_++) {
                const int mt = (wm << 2) + mt_;
                uint4 v = *reinterpret_cast<const uint4*>(&Asm[(((ks << 3) + mt) << 7) + (lsw << 2)]);
                A[mt_][0] = v.x; A[mt_][1] = v.y; A[mt_][2] = v.z; A[mt_][3] = v.w;
            }
            uint32_t B[4][2];
#pragma unroll
            for (int nt_ = 0; nt_ < 4; nt_++) {
                const int nt = (wn << 2) + nt_;
                uint2 v = *reinterpret_cast<const uint2*>(&Bsm[(((ks << 4) + nt) << 6) + (lsw << 1)]);
                B[nt_][0] = v.x; B[nt_][1] = v.y;
            }
#pragma unroll
            for (int mt_ = 0; mt_ < 4; mt_++)
#pragma unroll
                for (int nt_ = 0; nt_ < 4; nt_++)
                    mma_f16(acc[mt_][nt_], A[mt_], B[nt_]);
        }
    }
    __syncthreads();   // mainloop smem dead; SRow/SCol/Tsm reuse below

    const float invT = 10.f;
    const int g  = lane >> 2;
    const int tq = lane & 3;

    // does this tile intersect any same-class (positive) block?
    bool storeT;
    {
        const int r0 = row0, r1 = row0 + 128, c0 = col0, c1 = col0 + 128;
        storeT = (r0 < b1 && r1 > 0  && c0 < b1 && c1 > 0)
              || (r0 < b2 && r1 > b1 && c0 < b2 && c1 > b1)
              || (r0 < NV && r1 > b2 && c0 < NV && c1 > b2);
    }
    // tile fully inside ONE same-class block -> all exp partials masked out
    const bool allsame =
        (clsof(row0, b1, b2, NV) == clsof(row0 + 127, b1, b2, NV)) &&
        (clsof(col0, b1, b2, NV) == clsof(col0 + 127, b1, b2, NV)) &&
        (clsof(row0, b1, b2, NV) == clsof(col0, b1, b2, NV)) &&
        (clsof(row0, b1, b2, NV) != 3);

    // -- direct S store (only if class-intersecting) --
    if (storeT) {
        __half* __restrict__ S = g_S;
#pragma unroll
        for (int mt_ = 0; mt_ < 4; mt_++) {
            const int row = row0 + (wm << 6) + (mt_ << 4) + g;
#pragma unroll
            for (int nt_ = 0; nt_ < 4; nt_++) {
                const int col = col0 + (wn << 5) + (nt_ << 3) + (tq << 1);
                __half2 lo = __floats2half2_rn(acc[mt_][nt_][0] * invT, acc[mt_][nt_][1] * invT);
                __half2 hi = __floats2half2_rn(acc[mt_][nt_][2] * invT, acc[mt_][nt_][3] * invT);
                *reinterpret_cast<__half2*>(&S[(size_t)row * N + col]) = lo;
                *reinterpret_cast<__half2*>(&S[(size_t)(row + 8) * N + col]) = hi;
            }
        }
    }

    // -- masked exp partials (skipped entirely for all-same-class tiles) --
    float rsum[8] = {0, 0, 0, 0, 0, 0, 0, 0};
    float csum[8] = {0, 0, 0, 0, 0, 0, 0, 0};
    if (!allsame) {
        int rcls[8], ccls[8];
#pragma unroll
        for (int mt_ = 0; mt_ < 4; mt_++)
#pragma unroll
            for (int h = 0; h < 2; h++) {
                const int r = row0 + (wm << 6) + (mt_ << 4) + g + 8 * h;
                rcls[mt_ * 2 + h] = clsof(r, b1, b2, NV);
            }
#pragma unroll
        for (int nt_ = 0; nt_ < 4; nt_++)
#pragma unroll
            for (int c = 0; c < 2; c++) {
                const int cc = col0 + (wn << 5) + (nt_ << 3) + (tq << 1) + c;
                ccls[nt_ * 2 + c] = clsof(cc, b1, b2, NV);
            }

#pragma unroll
        for (int mt_ = 0; mt_ < 4; mt_++)
#pragma unroll
            for (int h = 0; h < 2; h++) {
                const int rc = rcls[mt_ * 2 + h];
#pragma unroll
                for (int nt_ = 0; nt_ < 4; nt_++)
#pragma unroll
                    for (int c = 0; c < 2; c++) {
                        const int cc = ccls[nt_ * 2 + c];
                        const float s = acc[mt_][nt_][2 * h + c] * invT;
                        const float e = __expf(s - 10.f);
                        const bool m = (rc != cc) && (rc != 3) && (cc != 3);
                        const float ev = m ? e : 0.f;
                        rsum[mt_ * 2 + h] += ev;
                        csum[nt_ * 2 + c] += ev;
                    }
            }
#pragma unroll
        for (int k = 0; k < 8; k++) {
            rsum[k] += __shfl_xor_sync(0xffffffffu, rsum[k], 1);
            rsum[k] += __shfl_xor_sync(0xffffffffu, rsum[k], 2);
            csum[k] += __shfl_xor_sync(0xffffffffu, csum[k], 4);
            csum[k] += __shfl_xor_sync(0xffffffffu, csum[k], 8);
            csum[k] += __shfl_xor_sync(0xffffffffu, csum[k], 16);
        }
    }
    if (tq == 0) {
#pragma unroll
        for (int mt_ = 0; mt_ < 4; mt_++)
#pragma unroll
            for (int h = 0; h < 2; h++) {
                const int rl = (wm << 6) + (mt_ << 4) + g + 8 * h;
                SRow[rl * 4 + wn] = rsum[mt_ * 2 + h];
            }
    }
    if (g == 0) {
#pragma unroll
        for (int nt_ = 0; nt_ < 4; nt_++)
#pragma unroll
            for (int c = 0; c < 2; c++) {
                const int cl = (wn << 5) + (nt_ << 3) + (tq << 1) + c;
                SCol[cl * 2 + wm] = csum[nt_ * 2 + c];
            }
    }
    __syncthreads();

    if (tid < 128) {
        const float rp = SRow[tid * 4 + 0] + SRow[tid * 4 + 1]
                       + SRow[tid * 4 + 2] + SRow[tid * 4 + 3];
        g_negpart[(size_t)(row0 + tid) * 64 + bx] = rp;
    } else if (bx != by) {
        const int c = tid - 128;
        const float cp = SCol[c * 2 + 0] + SCol[c * 2 + 1];
        g_negpart[(size_t)(col0 + c) * 64 + by] = cp;
    }

    // -- mirror S store (class-intersecting, off-diagonal) --
    if (storeT && bx != by) {
        __syncthreads();
#pragma unroll
        for (int mt_ = 0; mt_ < 4; mt_++) {
            const int r = (wm << 6) + (mt_ << 4) + g;
#pragma unroll
            for (int nt_ = 0; nt_ < 4; nt_++) {
                const int c = (wn << 5) + (nt_ << 3) + (tq << 1);
                Tsm[(c) * 136 + r]         = __float2half_rn(acc[mt_][nt_][0] * invT);
                Tsm[(c + 1) * 136 + r]     = __float2half_rn(acc[mt_][nt_][1] * invT);
                Tsm[(c) * 136 + r + 8]     = __float2half_rn(acc[mt_][nt_][2] * invT);
                Tsm[(c + 1) * 136 + r + 8] = __float2half_rn(acc[mt_][nt_][3] * invT);
            }
        }
        __syncthreads();
        const int tr  = tid >> 1;
        const int seg = (tid & 1) << 6;
        const uint4* src = reinterpret_cast<const uint4*>(&Tsm[tr * 136 + seg]);
        uint4* dst = reinterpret_cast<uint4*>(&g_S[(size_t)(col0 + tr) * N + row0 + seg]);
#pragma unroll
        for (int k = 0; k < 8; k++) dst[k] = src[k];
    }
}

// ---------------- kernel 3: per-row loss + fused final reduction ------------
__global__ void __launch_bounds__(256) k_rowloss(float* __restrict__ out, int N)
{
    __shared__ float redf[8];
    __shared__ float sL;
    __shared__ int   slast;

    const int i = blockIdx.x;
    const int tid = threadIdx.x;

    const int b1 = g_bnd[1];
    const int b2 = g_bnd[2];
    const int NV = g_bnd[3];

    float loss = 0.f;
    int   flag = 0;

    if (i < NV) {
        const int lo = (i < b1) ? 0  : ((i < b2) ? b1 : b2);
        const int hi = (i < b1) ? b1 : ((i < b2) ? b2 : NV);
        const int P  = hi - lo - 1;
        const int ntv = (NV + 127) >> 7;

        // negsum from precomputed tile partials (fixed order)
        float ns = (tid < ntv) ? g_negpart[(size_t)i * 64 + tid] : 0.f;
        ns = wred_f(ns);
        if ((tid & 31) == 0) redf[tid >> 5] = ns;
        __syncthreads();
        if (tid == 0) {
            float tt = 0.f;
#pragma unroll
            for (int w = 0; w < 8; w++) tt += redf[w];
            sL = (tt > 0.f) ? (__logf(tt) + 10.f) : -1e30f;
        }
        __syncthreads();
        const float L = sL;

        if (L > -1e29f) {
            if (P == 0) {
                loss = softplus_fast(L - 10.f);
                flag = 0;
            } else {
                const __half* __restrict__ row = g_S + (size_t)i * N;
                const uint4* __restrict__ rv = reinterpret_cast<const uint4*>(row);

                float psum = 0.f;
                const int v0 = lo >> 3;
                const int v1 = (hi + 7) >> 3;
                for (int v = v0 + tid; v < v1; v += 256) {
                    uint4 w = rv[v];
                    const int j0 = v << 3;
                    float s[8];
                    {
                        float2 f;
                        f = __half22float2(*reinterpret_cast<__half2*>(&w.x)); s[0] = f.x; s[1] = f.y;
                        f = __half22float2(*reinterpret_cast<__half2*>(&w.y)); s[2] = f.x; s[3] = f.y;
                        f = __half22float2(*reinterpret_cast<__half2*>(&w.z)); s[4] = f.x; s[5] = f.y;
                        f = __half22float2(*reinterpret_cast<__half2*>(&w.w)); s[6] = f.x; s[7] = f.y;
                    }
                    const bool interior = (j0 >= lo) && (j0 + 8 <= hi) &&
                                          ((i < j0) || (i >= j0 + 8));
                    if (interior) {
#pragma unroll
                        for (int k = 0; k < 8; k++)
                            psum += softplus_fast(L - s[k]);
                    } else {
#pragma unroll
                        for (int k = 0; k < 8; k++) {
                            const int j = j0 + k;
                            const bool m = (j >= lo) && (j < hi) && (j != i);
                            psum += m ? softplus_fast(L - s[k]) : 0.f;
                        }
                    }
                }
                psum = wred_f(psum);
                if ((tid & 31) == 0) redf[tid >> 5] = psum;
                __syncthreads();
                if (tid == 0) {
                    float tt = 0.f;
#pragma unroll
                    for (int w = 0; w < 8; w++) tt += redf[w];
                    loss = tt / (float)P;
                }
                flag = 1;
            }
        }
    }

    if (tid == 0) {
        g_rowloss[i] = loss;
        g_rowflag[i] = flag;
        __threadfence();
        int old = atomicAdd(&g_ctr, 1);
        slast = (old == gridDim.x - 1) ? 1 : 0;
    }
    __syncthreads();

    // last block performs the deterministic final reduction
    if (slast) {
        __threadfence();   // acquire: make all blocks' results visible
        const float4* rl = reinterpret_cast<const float4*>(g_rowloss);
        const int4*   fl = reinterpret_cast<const int4*>(g_rowflag);
        float s = 0.f;
        int c = 0;
        for (int v = tid; v < N / 4; v += 256) {
            float4 a = rl[v];
            int4   b = fl[v];
            s += a.x + a.y + a.z + a.w;
            c += b.x + b.y + b.z + b.w;
        }
        s = wred_f(s);
        c = wred_i(c);
        __shared__ float rf2[8];
        __shared__ int   ri2[8];
        if ((tid & 31) == 0) { rf2[tid >> 5] = s; ri2[tid >> 5] = c; }
        __syncthreads();
        if (tid == 0) {
            float tt = 0.f; int p = 0;
#pragma unroll
            for (int w = 0; w < 8; w++) { tt += rf2[w]; p += ri2[w]; }
            out[0] = tt / (float)(1 + p);
            g_ctr = 0;     // reset for next replay
        }
    }
}

// ---------------- launcher ---------------------------------------------------
extern "C" void kernel_launch(void* const* d_in, const int* in_sizes, int n_in,
                              void* d_out, int out_size)
{
    const float* feats  = (const float*)d_in[0];
    const int*   labels = (const int*)d_in[1];
    const int*   bad    = (const int*)d_in[2];
    float* out = (float*)d_out;

    const int N = in_sizes[1];            // 8192
    const int D = in_sizes[0] / N;        // 512

    k_perm<<<1, 1024>>>(labels, bad, N);
    k_normalize<<<N, 128>>>(feats, N, D);

    const int ntiles = (NTILE * (NTILE + 1)) / 2;   // 2080 (most exit early)
    k_gemm_f16<<<ntiles, 256>>>(N, D);

    k_rowloss<<<N, 256>>>(out, N);
}

// round 8
// speedup vs baseline: 1.0975x; 1.0975x over previous
#include <cuda_runtime.h>
#include <cuda_fp16.h>
#include <math.h>
#include <stdint.h>

// Shapes fixed by the problem: N=8192, D=512, 3 classes
#define NMAX 8192
#define DMAX 512

// ---------------- device scratch (static, no runtime allocation) ------------
__device__ __half g_fh[(size_t)NMAX * DMAX];   // permuted normalized features (8 MB)
__device__ __half g_S[(size_t)NMAX * NMAX];    // scaled logits, fp16 (class tiles only)
__device__ float  g_negpart[(size_t)NMAX * 64];// per-(row, col-tile) exp partials (2 MB)
__device__ int    g_perm[NMAX];                // sorted order: class0,1,2 valid, invalid
__device__ int    g_bnd[4];                    // {0, b1, b2, NV}
__device__ float  g_rowloss[NMAX];
__device__ int    g_rowflag[NMAX];

// ---------------- helpers ----------------------------------------------------
__device__ __forceinline__ float wred_f(float x) {
#pragma unroll
    for (int o = 16; o; o >>= 1) x += __shfl_xor_sync(0xffffffffu, x, o);
    return x;
}
__device__ __forceinline__ int wred_i(int x) {
#pragma unroll
    for (int o = 16; o; o >>= 1) x += __shfl_xor_sync(0xffffffffu, x, o);
    return x;
}

// exact softplus via fast MUFU paths: log1p(exp(d)) = max(d,0) + log(1+exp(-|d|))
__device__ __forceinline__ float softplus_fast(float d) {
    return fmaxf(d, 0.f) + __logf(1.f + __expf(-fabsf(d)));
}

__device__ __forceinline__ void mma_f16(float* d, const uint32_t* a, const uint32_t* b) {
    asm volatile(
        "mma.sync.aligned.m16n8k16.row.col.f32.f16.f16.f32 "
        "{%0,%1,%2,%3}, {%4,%5,%6,%7}, {%8,%9}, {%0,%1,%2,%3};"
        : "+f"(d[0]), "+f"(d[1]), "+f"(d[2]), "+f"(d[3])
        : "r"(a[0]), "r"(a[1]), "r"(a[2]), "r"(a[3]),
          "r"(b[0]), "r"(b[1]));
}

// ---------------- kernel 0: stable counting sort (1 block, warp scans) ------
__global__ void __launch_bounds__(1024) k_perm(
    const int* __restrict__ labels,
    const int* __restrict__ bad,
    int N)
{
    __shared__ uint32_t wt01[32], wt23[32];
    const int t = threadIdx.x;
    const int lane = t & 31;
    const int wid = t >> 5;

    const int4* lab4 = reinterpret_cast<const int4*>(labels);
    const int4* bad4 = reinterpret_cast<const int4*>(bad);
    int4 l0 = lab4[t * 2], l1 = lab4[t * 2 + 1];
    int4 d0 = bad4[t * 2], d1 = bad4[t * 2 + 1];

    int code[8];
    code[0] = (d0.x == 0) ? l0.x : 3;
    code[1] = (d0.y == 0) ? l0.y : 3;
    code[2] = (d0.z == 0) ? l0.z : 3;
    code[3] = (d0.w == 0) ? l0.w : 3;
    code[4] = (d1.x == 0) ? l1.x : 3;
    code[5] = (d1.y == 0) ? l1.y : 3;
    code[6] = (d1.z == 0) ? l1.z : 3;
    code[7] = (d1.w == 0) ? l1.w : 3;

    int cnt[4] = {0, 0, 0, 0};
#pragma unroll
    for (int e = 0; e < 8; e++) cnt[code[e]]++;

    uint32_t v01 = (uint32_t)cnt[0] | ((uint32_t)cnt[1] << 16);
    uint32_t v23 = (uint32_t)cnt[2] | ((uint32_t)cnt[3] << 16);
    uint32_t s01 = v01, s23 = v23;
#pragma unroll
    for (int off = 1; off < 32; off <<= 1) {
        uint32_t t1 = __shfl_up_sync(0xffffffffu, s01, off);
        uint32_t t2 = __shfl_up_sync(0xffffffffu, s23, off);
        if (lane >= off) { s01 += t1; s23 += t2; }
    }
    if (lane == 31) { wt01[wid] = s01; wt23[wid] = s23; }
    __syncthreads();
    if (wid == 0) {
        uint32_t w1 = wt01[lane], w2 = wt23[lane];
#pragma unroll
        for (int off = 1; off < 32; off <<= 1) {
            uint32_t t1 = __shfl_up_sync(0xffffffffu, w1, off);
            uint32_t t2 = __shfl_up_sync(0xffffffffu, w2, off);
            if (lane >= off) { w1 += t1; w2 += t2; }
        }
        wt01[lane] = w1; wt23[lane] = w2;
    }
    __syncthreads();

    const uint32_t wp01 = wid ? wt01[wid - 1] : 0u;
    const uint32_t wp23 = wid ? wt23[wid - 1] : 0u;
    const uint32_t tt01 = wt01[31], tt23 = wt23[31];

    const uint32_t ep01 = wp01 + s01 - v01;
    const uint32_t ep23 = wp23 + s23 - v23;
    int pre[4] = { (int)(ep01 & 0xffffu), (int)(ep01 >> 16),
                   (int)(ep23 & 0xffffu), (int)(ep23 >> 16) };
    const int tot0 = (int)(tt01 & 0xffffu);
    const int tot1 = (int)(tt01 >> 16);
    const int tot2 = (int)(tt23 & 0xffffu);
    int base[4] = { 0, tot0, tot0 + tot1, tot0 + tot1 + tot2 };

    int r[4] = {0, 0, 0, 0};
#pragma unroll
    for (int e = 0; e < 8; e++) {
        const int j = t * 8 + e;
        const int c = code[e];
        g_perm[base[c] + pre[c] + r[c]] = j;
        r[c]++;
    }
    if (t == 0) {
        g_bnd[0] = 0;
        g_bnd[1] = base[1];
        g_bnd[2] = base[2];
        g_bnd[3] = base[3];              // NV
    }
}

// ---------------- kernel 1: normalize + gather-permute -> fp16 --------------
__global__ void __launch_bounds__(128) k_normalize(
    const float* __restrict__ feats, int N, int D)
{
    const int i = blockIdx.x;
    const int tid = threadIdx.x;
    const int src = g_perm[i];
    float4 v = reinterpret_cast<const float4*>(feats + (size_t)src * D)[tid];
    float ss = v.x * v.x + v.y * v.y + v.z * v.z + v.w * v.w;
    ss = wred_f(ss);
    __shared__ float w[4];
    if ((tid & 31) == 0) w[tid >> 5] = ss;
    __syncthreads();
    float rinv = rsqrtf(w[0] + w[1] + w[2] + w[3]);
    uint2 o;
    __half2 h0 = __floats2half2_rn(v.x * rinv, v.y * rinv);
    __half2 h1 = __floats2half2_rn(v.z * rinv, v.w * rinv);
    o.x = *reinterpret_cast<uint32_t*>(&h0);
    o.y = *reinterpret_cast<uint32_t*>(&h1);
    reinterpret_cast<uint2*>(g_fh + (size_t)i * D)[tid] = o;
}

// ---------------- kernel 2: symmetric fp16 GEMM + fused neg-exp partials ----
#define NTILE 64  // N / 128 (max)

__device__ __forceinline__ int clsof(int x, int b1, int b2, int NV) {
    return (x < b1) ? 0 : (x < b2) ? 1 : (x < NV) ? 2 : 3;
}

__global__ void __launch_bounds__(256) k_gemm_f16(int N, int D)
{
    __shared__ __align__(16) unsigned char smem_raw[34816];
    uint32_t* Asm = reinterpret_cast<uint32_t*>(smem_raw);
    uint32_t* Bsm = reinterpret_cast<uint32_t*>(smem_raw + 16384);
    __half*   Tsm = reinterpret_cast<__half*>(smem_raw);
    float*    SRow = reinterpret_cast<float*>(smem_raw);          // [128][4]
    float*    SCol = reinterpret_cast<float*>(smem_raw + 2048);   // [128][2]

    int t = blockIdx.x;
    int by = 0;
    {
        int rem = t;
        while (rem >= NTILE - by) { rem -= NTILE - by; by++; }
        t = rem;
    }
    const int bx = by + t;

    const int b1 = g_bnd[1];
    const int b2 = g_bnd[2];
    const int NV = g_bnd[3];
    const int ntv = (NV + 127) >> 7;
    if (bx >= ntv) return;

    const int row0 = by * 128;
    const int col0 = bx * 128;

    const int tid  = threadIdx.x;
    const int lane = tid & 31;
    const int warp = tid >> 5;
    const int wm   = warp >> 2;
    const int wn   = warp & 3;

    const int lr  = tid >> 3;
    const int lc2 = (tid & 7) << 2;

    const int D2 = D >> 1;
    const uint32_t* __restrict__ fh2 = reinterpret_cast<const uint32_t*>(g_fh);

    float acc[4][4][4];
#pragma unroll
    for (int a = 0; a < 4; a++)
#pragma unroll
        for (int b = 0; b < 4; b++)
#pragma unroll
            for (int c = 0; c < 4; c++) acc[a][b][c] = 0.f;

    uint4 a4[4], b4[4];
#pragma unroll
    for (int r = 0; r < 4; r++) {
        a4[r] = *reinterpret_cast<const uint4*>(fh2 + (size_t)(row0 + lr + 32 * r) * D2 + lc2);
        b4[r] = *reinterpret_cast<const uint4*>(fh2 + (size_t)(col0 + lr + 32 * r) * D2 + lc2);
    }

    for (int k0 = 0; k0 < D2; k0 += 32) {
        __syncthreads();
#pragma unroll
        for (int r = 0; r < 4; r++) {
            const uint32_t av[4] = {a4[r].x, a4[r].y, a4[r].z, a4[r].w};
            const uint32_t bv[4] = {b4[r].x, b4[r].y, b4[r].z, b4[r].w};
            const int m  = lr + 32 * r;
            const int mt = m >> 4, rr = m & 15;
            const int nt = m >> 3, cc = m & 7;
#pragma unroll
            for (int c = 0; c < 4; c++) {
                const int kc = lc2 + c;
                const int ks = kc >> 3, k7 = kc & 7;
                const int swz = 5 * ks;
                const int laneA = ((((rr & 7) << 2) | (k7 & 3)) ^ swz);
                const int regA  = (rr >> 3) | ((k7 >> 2) << 1);
                Asm[(((ks << 3) + mt) << 7) + (laneA << 2) + regA] = av[c];
                const int laneB = (((cc << 2) | (k7 & 3)) ^ swz);
                const int regB  = k7 >> 2;
                Bsm[(((ks << 4) + nt) << 6) + (laneB << 1) + regB] = bv[c];
            }
        }
        __syncthreads();

        if (k0 + 32 < D2) {
#pragma unroll
            for (int r = 0; r < 4; r++) {
                a4[r] = *reinterpret_cast<const uint4*>(fh2 + (size_t)(row0 + lr + 32 * r) * D2 + lc2 + k0 + 32);
                b4[r] = *reinterpret_cast<const uint4*>(fh2 + (size_t)(col0 + lr + 32 * r) * D2 + lc2 + k0 + 32);
            }
        }

#pragma unroll
        for (int ks = 0; ks < 4; ks++) {
            const int lsw = lane ^ (5 * ks);
            uint32_t A[4][4];
#pragma unroll
            for (int mt_ = 0; mt_ < 4; mt_++) {
                const int mt = (wm << 2) + mt_;
                uint4 v = *reinterpret_cast<const uint4*>(&Asm[(((ks << 3) + mt) << 7) + (lsw << 2)]);
                A[mt_][0] = v.x; A[mt_][1] = v.y; A[mt_][2] = v.z; A[mt_][3] = v.w;
            }
            uint32_t B[4][2];
#pragma unroll
            for (int nt_ = 0; nt_ < 4; nt_++) {
                const int nt = (wn << 2) + nt_;
                uint2 v = *reinterpret_cast<const uint2*>(&Bsm[(((ks << 4) + nt) << 6) + (lsw << 1)]);
                B[nt_][0] = v.x; B[nt_][1] = v.y;
            }
#pragma unroll
            for (int mt_ = 0; mt_ < 4; mt_++)
#pragma unroll
                for (int nt_ = 0; nt_ < 4; nt_++)
                    mma_f16(acc[mt_][nt_], A[mt_], B[nt_]);
        }
    }
    __syncthreads();   // mainloop smem dead; SRow/SCol/Tsm reuse below

    const float invT = 10.f;
    const int g  = lane >> 2;
    const int tq = lane & 3;

    // does this tile intersect any same-class (positive) block?
    bool storeT;
    {
        const int r0 = row0, r1 = row0 + 128, c0 = col0, c1 = col0 + 128;
        storeT = (r0 < b1 && r1 > 0  && c0 < b1 && c1 > 0)
              || (r0 < b2 && r1 > b1 && c0 < b2 && c1 > b1)
              || (r0 < NV && r1 > b2 && c0 < NV && c1 > b2);
    }
    // tile fully inside ONE same-class block -> all exp partials masked out
    const bool allsame =
        (clsof(row0, b1, b2, NV) == clsof(row0 + 127, b1, b2, NV)) &&
        (clsof(col0, b1, b2, NV) == clsof(col0 + 127, b1, b2, NV)) &&
        (clsof(row0, b1, b2, NV) == clsof(col0, b1, b2, NV)) &&
        (clsof(row0, b1, b2, NV) != 3);

    // -- direct S store (only if class-intersecting) --
    if (storeT) {
        __half* __restrict__ S = g_S;
#pragma unroll
        for (int mt_ = 0; mt_ < 4; mt_++) {
            const int row = row0 + (wm << 6) + (mt_ << 4) + g;
#pragma unroll
            for (int nt_ = 0; nt_ < 4; nt_++) {
                const int col = col0 + (wn << 5) + (nt_ << 3) + (tq << 1);
                __half2 lo = __floats2half2_rn(acc[mt_][nt_][0] * invT, acc[mt_][nt_][1] * invT);
                __half2 hi = __floats2half2_rn(acc[mt_][nt_][2] * invT, acc[mt_][nt_][3] * invT);
                *reinterpret_cast<__half2*>(&S[(size_t)row * N + col]) = lo;
                *reinterpret_cast<__half2*>(&S[(size_t)(row + 8) * N + col]) = hi;
            }
        }
    }

    // -- masked exp partials (skipped entirely for all-same-class tiles) --
    float rsum[8] = {0, 0, 0, 0, 0, 0, 0, 0};
    float csum[8] = {0, 0, 0, 0, 0, 0, 0, 0};
    if (!allsame) {
        int rcls[8], ccls[8];
#pragma unroll
        for (int mt_ = 0; mt_ < 4; mt_++)
#pragma unroll
            for (int h = 0; h < 2; h++) {
                const int r = row0 + (wm << 6) + (mt_ << 4) + g + 8 * h;
                rcls[mt_ * 2 + h] = clsof(r, b1, b2, NV);
            }
#pragma unroll
        for (int nt_ = 0; nt_ < 4; nt_++)
#pragma unroll
            for (int c = 0; c < 2; c++) {
                const int cc = col0 + (wn << 5) + (nt_ << 3) + (tq << 1) + c;
                ccls[nt_ * 2 + c] = clsof(cc, b1, b2, NV);
            }

#pragma unroll
        for (int mt_ = 0; mt_ < 4; mt_++)
#pragma unroll
            for (int h = 0; h < 2; h++) {
                const int rc = rcls[mt_ * 2 + h];
#pragma unroll
                for (int nt_ = 0; nt_ < 4; nt_++)
#pragma unroll
                    for (int c = 0; c < 2; c++) {
                        const int cc = ccls[nt_ * 2 + c];
                        const float s = acc[mt_][nt_][2 * h + c] * invT;
                        const float e = __expf(s - 10.f);
                        const bool m = (rc != cc) && (rc != 3) && (cc != 3);
                        const float ev = m ? e : 0.f;
                        rsum[mt_ * 2 + h] += ev;
                        csum[nt_ * 2 + c] += ev;
                    }
            }
#pragma unroll
        for (int k = 0; k < 8; k++) {
            rsum[k] += __shfl_xor_sync(0xffffffffu, rsum[k], 1);
            rsum[k] += __shfl_xor_sync(0xffffffffu, rsum[k], 2);
            csum[k] += __shfl_xor_sync(0xffffffffu, csum[k], 4);
            csum[k] += __shfl_xor_sync(0xffffffffu, csum[k], 8);
            csum[k] += __shfl_xor_sync(0xffffffffu, csum[k], 16);
        }
    }
    if (tq == 0) {
#pragma unroll
        for (int mt_ = 0; mt_ < 4; mt_++)
#pragma unroll
            for (int h = 0; h < 2; h++) {
                const int rl = (wm << 6) + (mt_ << 4) + g + 8 * h;
                SRow[rl * 4 + wn] = rsum[mt_ * 2 + h];
            }
    }
    if (g == 0) {
#pragma unroll
        for (int nt_ = 0; nt_ < 4; nt_++)
#pragma unroll
            for (int c = 0; c < 2; c++) {
                const int cl = (wn << 5) + (nt_ << 3) + (tq << 1) + c;
                SCol[cl * 2 + wm] = csum[nt_ * 2 + c];
            }
    }
    __syncthreads();

    if (tid < 128) {
        const float rp = SRow[tid * 4 + 0] + SRow[tid * 4 + 1]
                       + SRow[tid * 4 + 2] + SRow[tid * 4 + 3];
        g_negpart[(size_t)(row0 + tid) * 64 + bx] = rp;
    } else if (bx != by) {
        const int c = tid - 128;
        const float cp = SCol[c * 2 + 0] + SCol[c * 2 + 1];
        g_negpart[(size_t)(col0 + c) * 64 + by] = cp;
    }

    // -- mirror S store (class-intersecting, off-diagonal) --
    if (storeT && bx != by) {
        __syncthreads();
#pragma unroll
        for (int mt_ = 0; mt_ < 4; mt_++) {
            const int r = (wm << 6) + (mt_ << 4) + g;
#pragma unroll
            for (int nt_ = 0; nt_ < 4; nt_++) {
                const int c = (wn << 5) + (nt_ << 3) + (tq << 1);
                Tsm[(c) * 136 + r]         = __float2half_rn(acc[mt_][nt_][0] * invT);
                Tsm[(c + 1) * 136 + r]     = __float2half_rn(acc[mt_][nt_][1] * invT);
                Tsm[(c) * 136 + r + 8]     = __float2half_rn(acc[mt_][nt_][2] * invT);
                Tsm[(c + 1) * 136 + r + 8] = __float2half_rn(acc[mt_][nt_][3] * invT);
            }
        }
        __syncthreads();
        const int tr  = tid >> 1;
        const int seg = (tid & 1) << 6;
        const uint4* src = reinterpret_cast<const uint4*>(&Tsm[tr * 136 + seg]);
        uint4* dst = reinterpret_cast<uint4*>(&g_S[(size_t)(col0 + tr) * N + row0 + seg]);
#pragma unroll
        for (int k = 0; k < 8; k++) dst[k] = src[k];
    }
}

// ---------------- kernel 3: per-row loss (partials + fast softplus) ---------
__global__ void __launch_bounds__(256) k_rowloss(int N)
{
    __shared__ float redf[8];
    __shared__ float sL;

    const int i = blockIdx.x;
    const int tid = threadIdx.x;

    const int b1 = g_bnd[1];
    const int b2 = g_bnd[2];
    const int NV = g_bnd[3];

    if (i >= NV) {
        if (tid == 0) { g_rowloss[i] = 0.f; g_rowflag[i] = 0; }
        return;
    }

    const int lo = (i < b1) ? 0  : ((i < b2) ? b1 : b2);
    const int hi = (i < b1) ? b1 : ((i < b2) ? b2 : NV);
    const int P  = hi - lo - 1;
    const int ntv = (NV + 127) >> 7;

    // negsum from precomputed tile partials (fixed order)
    float ns = (tid < ntv) ? g_negpart[(size_t)i * 64 + tid] : 0.f;
    ns = wred_f(ns);
    if ((tid & 31) == 0) redf[tid >> 5] = ns;
    __syncthreads();
    if (tid == 0) {
        float tt = 0.f;
#pragma unroll
        for (int w = 0; w < 8; w++) tt += redf[w];
        sL = (tt > 0.f) ? (__logf(tt) + 10.f) : -1e30f;
    }
    __syncthreads();
    const float L = sL;

    if (L <= -1e29f) {                  // no negatives: not processed
        if (tid == 0) { g_rowloss[i] = 0.f; g_rowflag[i] = 0; }
        return;
    }
    if (P == 0) {                       // no positives: pos logit = 1/T = 10
        if (tid == 0) {
            g_rowloss[i] = softplus_fast(L - 10.f);
            g_rowflag[i] = 0;
        }
        return;
    }

    // pass 2: psum over positives [lo, hi) \ {i}, 8-wide with interior fast path
    const __half* __restrict__ row = g_S + (size_t)i * N;
    const uint4* __restrict__ rv = reinterpret_cast<const uint4*>(row);

    float psum = 0.f;
    const int v0 = lo >> 3;
    const int v1 = (hi + 7) >> 3;
    for (int v = v0 + tid; v < v1; v += 256) {
        uint4 w = rv[v];
        const int j0 = v << 3;
        float s[8];
        {
            float2 f;
            f = __half22float2(*reinterpret_cast<__half2*>(&w.x)); s[0] = f.x; s[1] = f.y;
            f = __half22float2(*reinterpret_cast<__half2*>(&w.y)); s[2] = f.x; s[3] = f.y;
            f = __half22float2(*reinterpret_cast<__half2*>(&w.z)); s[4] = f.x; s[5] = f.y;
            f = __half22float2(*reinterpret_cast<__half2*>(&w.w)); s[6] = f.x; s[7] = f.y;
        }
        const bool interior = (j0 >= lo) && (j0 + 8 <= hi) &&
                              ((i < j0) || (i >= j0 + 8));
        if (interior) {
#pragma unroll
            for (int k = 0; k < 8; k++)
                psum += softplus_fast(L - s[k]);
        } else {
#pragma unroll
            for (int k = 0; k < 8; k++) {
                const int j = j0 + k;
                const bool m = (j >= lo) && (j < hi) && (j != i);
                psum += m ? softplus_fast(L - s[k]) : 0.f;
            }
        }
    }
    psum = wred_f(psum);
    if ((tid & 31) == 0) redf[tid >> 5] = psum;
    __syncthreads();
    if (tid == 0) {
        float tt = 0.f;
#pragma unroll
        for (int w = 0; w < 8; w++) tt += redf[w];
        g_rowloss[i] = tt / (float)P;
        g_rowflag[i] = 1;
    }
}

// ---------------- kernel 4: final deterministic reduction -------------------
__global__ void __launch_bounds__(256) k_finalize(float* __restrict__ out, int N)
{
    const int tid = threadIdx.x;
    const float4* rl = reinterpret_cast<const float4*>(g_rowloss);
    const int4*   fl = reinterpret_cast<const int4*>(g_rowflag);
    float s = 0.f;
    int c = 0;
    for (int v = tid; v < N / 4; v += 256) {
        float4 a = rl[v];
        int4   b = fl[v];
        s += a.x + a.y + a.z + a.w;
        c += b.x + b.y + b.z + b.w;
    }
    s = wred_f(s);
    c = wred_i(c);
    __shared__ float redf[8];
    __shared__ int   redi[8];
    if ((tid & 31) == 0) { redf[tid >> 5] = s; redi[tid >> 5] = c; }
    __syncthreads();
    if (tid == 0) {
        float tt = 0.f; int p = 0;
#pragma unroll
        for (int w = 0; w < 8; w++) { tt += redf[w]; p += redi[w]; }
        out[0] = tt / (float)(1 + p);
    }
}

// ---------------- launcher ---------------------------------------------------
extern "C" void kernel_launch(void* const* d_in, const int* in_sizes, int n_in,
                              void* d_out, int out_size)
{
    const float* feats  = (const float*)d_in[0];
    const int*   labels = (const int*)d_in[1];
    const int*   bad    = (const int*)d_in[2];
    float* out = (float*)d_out;

    const int N = in_sizes[1];            // 8192
    const int D = in_sizes[0] / N;        // 512

    k_perm<<<1, 1024>>>(labels, bad, N);
    k_normalize<<<N, 128>>>(feats, N, D);

    const int ntiles = (NTILE * (NTILE + 1)) / 2;   // 2080 (most exit early)
    k_gemm_f16<<<ntiles, 256>>>(N, D);

    k_rowloss<<<N, 256>>>(N);
    k_finalize<<<1, 256>>>(out, N);
}

// round 10
// speedup vs baseline: 1.1788x; 1.0741x over previous
#include <cuda_runtime.h>
#include <cuda_fp16.h>
#include <math.h>
#include <stdint.h>

// Shapes fixed by the problem: N=8192, D=512, 3 classes
#define NMAX 8192
#define DMAX 512
#define NTILE 64   // N / 128

// ---------------- device scratch (static, no runtime allocation) ------------
__device__ __half g_fh[(size_t)NMAX * DMAX];   // permuted normalized features (8 MB)
__device__ __half g_S[(size_t)NMAX * NMAX];    // scaled logits, fp16 (class tiles only)
__device__ float  g_negpart[(size_t)NMAX * 64];// per-(row, col-tile) exp partials (2 MB)
__device__ int    g_perm[NMAX];
__device__ int    g_bnd[4];                    // {0, b1, b2, NV}
__device__ float  g_rowloss[NMAX];
__device__ int    g_rowflag[NMAX];

// ---------------- helpers ----------------------------------------------------
__device__ __forceinline__ float wred_f(float x) {
#pragma unroll
    for (int o = 16; o; o >>= 1) x += __shfl_xor_sync(0xffffffffu, x, o);
    return x;
}
__device__ __forceinline__ int wred_i(int x) {
#pragma unroll
    for (int o = 16; o; o >>= 1) x += __shfl_xor_sync(0xffffffffu, x, o);
    return x;
}
__device__ __forceinline__ float softplus_fast(float d) {
    return fmaxf(d, 0.f) + __logf(1.f + __expf(-fabsf(d)));
}
__device__ __forceinline__ int clsof(int x, int b1, int b2, int NV) {
    return (x < b1) ? 0 : (x < b2) ? 1 : (x < NV) ? 2 : 3;
}

__device__ __forceinline__ void mma_f16(float* d, const uint32_t* a, const uint32_t* b) {
    asm volatile(
        "mma.sync.aligned.m16n8k16.row.col.f32.f16.f16.f32 "
        "{%0,%1,%2,%3}, {%4,%5,%6,%7}, {%8,%9}, {%0,%1,%2,%3};"
        : "+f"(d[0]), "+f"(d[1]), "+f"(d[2]), "+f"(d[3])
        : "r"(a[0]), "r"(a[1]), "r"(a[2]), "r"(a[3]),
          "r"(b[0]), "r"(b[1]));
}
__device__ __forceinline__ void ldsm_x4(uint32_t* r, uint32_t a) {
    asm volatile("ldmatrix.sync.aligned.m8n8.x4.shared.b16 {%0,%1,%2,%3}, [%4];"
                 : "=r"(r[0]), "=r"(r[1]), "=r"(r[2]), "=r"(r[3]) : "r"(a));
}
__device__ __forceinline__ void ldsm_x2(uint32_t* r, uint32_t a) {
    asm volatile("ldmatrix.sync.aligned.m8n8.x2.shared.b16 {%0,%1}, [%2];"
                 : "=r"(r[0]), "=r"(r[1]) : "r"(a));
}
__device__ __forceinline__ void cp_async16(uint32_t dst, const void* src) {
    size_t g = __cvta_generic_to_global(src);
    asm volatile("cp.async.cg.shared.global [%0], [%1], 16;"
                 :: "r"(dst), "l"(g) : "memory");
}

// ---------------- kernel 0: stable counting sort (1 block, warp scans) ------
__global__ void __launch_bounds__(1024) k_perm(
    const int* __restrict__ labels,
    const int* __restrict__ bad,
    int N)
{
    __shared__ uint32_t wt01[32], wt23[32];
    const int t = threadIdx.x;
    const int lane = t & 31;
    const int wid = t >> 5;

    const int4* lab4 = reinterpret_cast<const int4*>(labels);
    const int4* bad4 = reinterpret_cast<const int4*>(bad);
    int4 l0 = lab4[t * 2], l1 = lab4[t * 2 + 1];
    int4 d0 = bad4[t * 2], d1 = bad4[t * 2 + 1];

    int code[8];
    code[0] = (d0.x == 0) ? l0.x : 3;
    code[1] = (d0.y == 0) ? l0.y : 3;
    code[2] = (d0.z == 0) ? l0.z : 3;
    code[3] = (d0.w == 0) ? l0.w : 3;
    code[4] = (d1.x == 0) ? l1.x : 3;
    code[5] = (d1.y == 0) ? l1.y : 3;
    code[6] = (d1.z == 0) ? l1.z : 3;
    code[7] = (d1.w == 0) ? l1.w : 3;

    int cnt[4] = {0, 0, 0, 0};
#pragma unroll
    for (int e = 0; e < 8; e++) cnt[code[e]]++;

    uint32_t v01 = (uint32_t)cnt[0] | ((uint32_t)cnt[1] << 16);
    uint32_t v23 = (uint32_t)cnt[2] | ((uint32_t)cnt[3] << 16);
    uint32_t s01 = v01, s23 = v23;
#pragma unroll
    for (int off = 1; off < 32; off <<= 1) {
        uint32_t t1 = __shfl_up_sync(0xffffffffu, s01, off);
        uint32_t t2 = __shfl_up_sync(0xffffffffu, s23, off);
        if (lane >= off) { s01 += t1; s23 += t2; }
    }
    if (lane == 31) { wt01[wid] = s01; wt23[wid] = s23; }
    __syncthreads();
    if (wid == 0) {
        uint32_t w1 = wt01[lane], w2 = wt23[lane];
#pragma unroll
        for (int off = 1; off < 32; off <<= 1) {
            uint32_t t1 = __shfl_up_sync(0xffffffffu, w1, off);
            uint32_t t2 = __shfl_up_sync(0xffffffffu, w2, off);
            if (lane >= off) { w1 += t1; w2 += t2; }
        }
        wt01[lane] = w1; wt23[lane] = w2;
    }
    __syncthreads();

    const uint32_t wp01 = wid ? wt01[wid - 1] : 0u;
    const uint32_t wp23 = wid ? wt23[wid - 1] : 0u;
    const uint32_t tt01 = wt01[31], tt23 = wt23[31];

    const uint32_t ep01 = wp01 + s01 - v01;
    const uint32_t ep23 = wp23 + s23 - v23;
    int pre[4] = { (int)(ep01 & 0xffffu), (int)(ep01 >> 16),
                   (int)(ep23 & 0xffffu), (int)(ep23 >> 16) };
    const int tot0 = (int)(tt01 & 0xffffu);
    const int tot1 = (int)(tt01 >> 16);
    const int tot2 = (int)(tt23 & 0xffffu);
    int base[4] = { 0, tot0, tot0 + tot1, tot0 + tot1 + tot2 };

    int r[4] = {0, 0, 0, 0};
#pragma unroll
    for (int e = 0; e < 8; e++) {
        const int j = t * 8 + e;
        const int c = code[e];
        g_perm[base[c] + pre[c] + r[c]] = j;
        r[c]++;
    }
    if (t == 0) {
        g_bnd[0] = 0;
        g_bnd[1] = base[1];
        g_bnd[2] = base[2];
        g_bnd[3] = base[3];
    }
}

// ---------------- kernel 1: normalize + gather-permute -> fp16 --------------
__global__ void __launch_bounds__(128) k_normalize(
    const float* __restrict__ feats, int N, int D)
{
    const int i = blockIdx.x;
    const int tid = threadIdx.x;
    const int src = g_perm[i];
    float4 v = reinterpret_cast<const float4*>(feats + (size_t)src * D)[tid];
    float ss = v.x * v.x + v.y * v.y + v.z * v.z + v.w * v.w;
    ss = wred_f(ss);
    __shared__ float w[4];
    if ((tid & 31) == 0) w[tid >> 5] = ss;
    __syncthreads();
    float rinv = rsqrtf(w[0] + w[1] + w[2] + w[3]);
    uint2 o;
    __half2 h0 = __floats2half2_rn(v.x * rinv, v.y * rinv);
    __half2 h1 = __floats2half2_rn(v.z * rinv, v.w * rinv);
    o.x = *reinterpret_cast<uint32_t*>(&h0);
    o.y = *reinterpret_cast<uint32_t*>(&h1);
    reinterpret_cast<uint2*>(g_fh + (size_t)i * D)[tid] = o;
}

// ---------------- kernel 2: fp16 GEMM (cp.async + ldmatrix) + partials ------
// 128x128 upper-triangle tiles over the valid block. A/B row-major SW128
// smem, double-buffered cp.async; ldmatrix feeds m16n8k16 HMMA. Epilogue
// computes masked exp(s-10) row/col partials and stores S for
// class-intersecting tiles (mirror via smem transpose).
#define TCB 256
#define SM_A0 0
#define SM_A1 16384
#define SM_B0 32768
#define SM_B1 49152
#define SM_DYN 65536

__global__ void __launch_bounds__(TCB) k_gemm_f16(int N, int D)
{
    extern __shared__ __align__(16) unsigned char dsm[];
    const uint32_t sbase = (uint32_t)__cvta_generic_to_shared(dsm);

    // linear block id -> upper-triangle (by, bx), bx >= by
    int t = blockIdx.x;
    int by = 0;
    {
        int rem = t;
        while (rem >= NTILE - by) { rem -= NTILE - by; by++; }
        t = rem;
    }
    const int bx = by + t;

    const int b1 = g_bnd[1];
    const int b2 = g_bnd[2];
    const int NV = g_bnd[3];
    const int ntv = (NV + 127) >> 7;
    if (bx >= ntv) return;

    const int row0 = by * 128;
    const int col0 = bx * 128;

    const int tid  = threadIdx.x;
    const int lane = tid & 31;
    const int warp = tid >> 5;
    const int wm   = warp >> 2;       // 0..1 (64 rows each)
    const int wn   = warp & 3;        // 0..3 (32 cols each)

    const __half* __restrict__ fA = g_fh + (size_t)row0 * D;
    const __half* __restrict__ fB = g_fh + (size_t)col0 * D;

    const uint32_t aB[2] = {sbase + SM_A0, sbase + SM_A1};
    const uint32_t bB[2] = {sbase + SM_B0, sbase + SM_B1};

    // cp.async write pattern (shared per-thread): 4 16B chunks per matrix
    int cp_r[4], cp_sw[4];
#pragma unroll
    for (int i = 0; i < 4; i++) {
        const int e = tid + i * TCB;       // 0..1023
        const int r = e >> 3, g = e & 7;
        cp_r[i]  = r;
        cp_sw[i] = r * 128 + ((g * 16) ^ ((r & 7) << 4));
    }

    float acc[4][4][4];
#pragma unroll
    for (int a = 0; a < 4; a++)
#pragma unroll
        for (int b = 0; b < 4; b++)
#pragma unroll
            for (int c = 0; c < 4; c++) acc[a][b][c] = 0.f;

    // ldmatrix per-lane address precompute
    const int rr = lane & 7;
    const int xr = rr << 4;                 // swizzle XOR (constant per lane)
    const int qa = lane >> 3;               // 0..3 (A mat index)
    const int kA = (qa >> 1) << 4;          // A kgroup byte
    const int kB = ((lane >> 3) & 1) << 4;  // B kgroup byte
    int rowA[4], rowB[4];
#pragma unroll
    for (int mt = 0; mt < 4; mt++)
        rowA[mt] = ((wm << 6) + (mt << 4) + ((qa & 1) << 3) + rr) * 128;
#pragma unroll
    for (int nt = 0; nt < 4; nt++)
        rowB[nt] = ((wn << 5) + (nt << 3) + rr) * 128;

    const int NCH = D >> 6;                 // 8 chunks of 64 halves (128 B/row)

    // prologue: load chunk 0
    {
        const int koff = 0;
#pragma unroll
        for (int i = 0; i < 4; i++) {
            cp_async16(aB[0] + cp_sw[i], fA + (size_t)cp_r[i] * D + koff + ((tid + i * TCB) & 7) * 8);
            cp_async16(bB[0] + cp_sw[i], fB + (size_t)cp_r[i] * D + koff + ((tid + i * TCB) & 7) * 8);
        }
        asm volatile("cp.async.commit_group;" ::: "memory");
    }

    for (int c = 0; c < NCH; c++) {
        const int buf = c & 1;
        if (c + 1 < NCH) {
            const int koff = (c + 1) << 6;
            const int nb = (c + 1) & 1;
#pragma unroll
            for (int i = 0; i < 4; i++) {
                cp_async16(aB[nb] + cp_sw[i], fA + (size_t)cp_r[i] * D + koff + ((tid + i * TCB) & 7) * 8);
                cp_async16(bB[nb] + cp_sw[i], fB + (size_t)cp_r[i] * D + koff + ((tid + i * TCB) & 7) * 8);
            }
            asm volatile("cp.async.commit_group;" ::: "memory");
            asm volatile("cp.async.wait_group 1;" ::: "memory");
        } else {
            asm volatile("cp.async.wait_group 0;" ::: "memory");
        }
        __syncthreads();

        const uint32_t ab = aB[buf];
        const uint32_t bb = bB[buf];
#pragma unroll
        for (int ks = 0; ks < 4; ks++) {
            const int kk = ks << 5;
            uint32_t Af[4][4], Bf[4][2];
#pragma unroll
            for (int mt = 0; mt < 4; mt++)
                ldsm_x4(Af[mt], ab + rowA[mt] + ((kk + kA) ^ xr));
#pragma unroll
            for (int nt = 0; nt < 4; nt++)
                ldsm_x2(Bf[nt], bb + rowB[nt] + ((kk + kB) ^ xr));
#pragma unroll
            for (int mt = 0; mt < 4; mt++)
#pragma unroll
                for (int nt = 0; nt < 4; nt++)
                    mma_f16(acc[mt][nt], Af[mt], Bf[nt]);
        }
        __syncthreads();
    }

    // ---- epilogue (same structure as R8) ----
    float* SRow = reinterpret_cast<float*>(dsm);           // [128][4]
    float* SCol = reinterpret_cast<float*>(dsm + 2048);    // [128][2]
    __half* Tsm = reinterpret_cast<__half*>(dsm);          // reuse (34816 B)

    const float invT = 10.f;
    const int g  = lane >> 2;
    const int tq = lane & 3;

    bool storeT;
    {
        const int r0 = row0, r1 = row0 + 128, c0 = col0, c1 = col0 + 128;
        storeT = (r0 < b1 && c0 < b1)
              || (r0 < b2 && r1 > b1 && c0 < b2 && c1 > b1)
              || (r1 > b2 && c1 > b2 && row0 < NV && col0 < NV);
    }
    const bool allsame =
        (clsof(row0, b1, b2, NV) == clsof(row0 + 127, b1, b2, NV)) &&
        (clsof(col0, b1, b2, NV) == clsof(col0 + 127, b1, b2, NV)) &&
        (clsof(row0, b1, b2, NV) == clsof(col0, b1, b2, NV)) &&
        (clsof(row0, b1, b2, NV) != 3);

    if (storeT) {
        __half* __restrict__ S = g_S;
#pragma unroll
        for (int mt = 0; mt < 4; mt++) {
            const int row = row0 + (wm << 6) + (mt << 4) + g;
#pragma unroll
            for (int nt = 0; nt < 4; nt++) {
                const int col = col0 + (wn << 5) + (nt << 3) + (tq << 1);
                __half2 lo = __floats2half2_rn(acc[mt][nt][0] * invT, acc[mt][nt][1] * invT);
                __half2 hi = __floats2half2_rn(acc[mt][nt][2] * invT, acc[mt][nt][3] * invT);
                *reinterpret_cast<__half2*>(&S[(size_t)row * N + col]) = lo;
                *reinterpret_cast<__half2*>(&S[(size_t)(row + 8) * N + col]) = hi;
            }
        }
    }

    float rsum[8] = {0, 0, 0, 0, 0, 0, 0, 0};
    float csum[8] = {0, 0, 0, 0, 0, 0, 0, 0};
    if (!allsame) {
        int rcls[8], ccls[8];
#pragma unroll
        for (int mt = 0; mt < 4; mt++)
#pragma unroll
            for (int h = 0; h < 2; h++) {
                const int r = row0 + (wm << 6) + (mt << 4) + g + 8 * h;
                rcls[mt * 2 + h] = clsof(r, b1, b2, NV);
            }
#pragma unroll
        for (int nt = 0; nt < 4; nt++)
#pragma unroll
            for (int c = 0; c < 2; c++) {
                const int cc = col0 + (wn << 5) + (nt << 3) + (tq << 1) + c;
                ccls[nt * 2 + c] = clsof(cc, b1, b2, NV);
            }
#pragma unroll
        for (int mt = 0; mt < 4; mt++)
#pragma unroll
            for (int h = 0; h < 2; h++) {
                const int rc = rcls[mt * 2 + h];
#pragma unroll
                for (int nt = 0; nt < 4; nt++)
#pragma unroll
                    for (int c = 0; c < 2; c++) {
                        const int cc = ccls[nt * 2 + c];
                        const float s = acc[mt][nt][2 * h + c] * invT;
                        const float e = __expf(s - 10.f);
                        const bool m = (rc != cc) && (rc != 3) && (cc != 3);
                        const float ev = m ? e : 0.f;
                        rsum[mt * 2 + h] += ev;
                        csum[nt * 2 + c] += ev;
                    }
            }
#pragma unroll
        for (int k = 0; k < 8; k++) {
            rsum[k] += __shfl_xor_sync(0xffffffffu, rsum[k], 1);
            rsum[k] += __shfl_xor_sync(0xffffffffu, rsum[k], 2);
            csum[k] += __shfl_xor_sync(0xffffffffu, csum[k], 4);
            csum[k] += __shfl_xor_sync(0xffffffffu, csum[k], 8);
            csum[k] += __shfl_xor_sync(0xffffffffu, csum[k], 16);
        }
    }
    if (tq == 0) {
#pragma unroll
        for (int mt = 0; mt < 4; mt++)
#pragma unroll
            for (int h = 0; h < 2; h++) {
                const int rl = (wm << 6) + (mt << 4) + g + 8 * h;
                SRow[rl * 4 + wn] = rsum[mt * 2 + h];
            }
    }
    if (g == 0) {
#pragma unroll
        for (int nt = 0; nt < 4; nt++)
#pragma unroll
            for (int c = 0; c < 2; c++) {
                const int cl = (wn << 5) + (nt << 3) + (tq << 1) + c;
                SCol[cl * 2 + wm] = csum[nt * 2 + c];
            }
    }
    __syncthreads();

    if (tid < 128) {
        const float rp = SRow[tid * 4 + 0] + SRow[tid * 4 + 1]
                       + SRow[tid * 4 + 2] + SRow[tid * 4 + 3];
        g_negpart[(size_t)(row0 + tid) * 64 + bx] = rp;
    } else if (bx != by) {
        const int c = tid - 128;
        const float cp = SCol[c * 2 + 0] + SCol[c * 2 + 1];
        g_negpart[(size_t)(col0 + c) * 64 + by] = cp;
    }

    if (storeT && bx != by) {
        __syncthreads();
#pragma unroll
        for (int mt = 0; mt < 4; mt++) {
            const int r = (wm << 6) + (mt << 4) + g;
#pragma unroll
            for (int nt = 0; nt < 4; nt++) {
                const int c = (wn << 5) + (nt << 3) + (tq << 1);
                Tsm[(c) * 136 + r]         = __float2half_rn(acc[mt][nt][0] * invT);
                Tsm[(c + 1) * 136 + r]     = __float2half_rn(acc[mt][nt][1] * invT);
                Tsm[(c) * 136 + r + 8]     = __float2half_rn(acc[mt][nt][2] * invT);
                Tsm[(c + 1) * 136 + r + 8] = __float2half_rn(acc[mt][nt][3] * invT);
            }
        }
        __syncthreads();
        const int tr  = tid >> 1;
        const int seg = (tid & 1) << 6;
        const uint4* src = reinterpret_cast<const uint4*>(&Tsm[tr * 136 + seg]);
        uint4* dst = reinterpret_cast<uint4*>(&g_S[(size_t)(col0 + tr) * N + row0 + seg]);
#pragma unroll
        for (int k = 0; k < 8; k++) dst[k] = src[k];
    }
}

// ---------------- kernel 3: per-row loss (partials + fast softplus) ---------
__global__ void __launch_bounds__(256) k_rowloss(int N)
{
    __shared__ float redf[8];
    __shared__ float sL;

    const int i = blockIdx.x;
    const int tid = threadIdx.x;

    const int b1 = g_bnd[1];
    const int b2 = g_bnd[2];
    const int NV = g_bnd[3];

    if (i >= NV) {
        if (tid == 0) { g_rowloss[i] = 0.f; g_rowflag[i] = 0; }
        return;
    }

    const int lo = (i < b1) ? 0  : ((i < b2) ? b1 : b2);
    const int hi = (i < b1) ? b1 : ((i < b2) ? b2 : NV);
    const int P  = hi - lo - 1;
    const int ntv = (NV + 127) >> 7;

    float ns = (tid < ntv) ? g_negpart[(size_t)i * 64 + tid] : 0.f;
    ns = wred_f(ns);
    if ((tid & 31) == 0) redf[tid >> 5] = ns;
    __syncthreads();
    if (tid == 0) {
        float tt = 0.f;
#pragma unroll
        for (int w = 0; w < 8; w++) tt += redf[w];
        sL = (tt > 0.f) ? (__logf(tt) + 10.f) : -1e30f;
    }
    __syncthreads();
    const float L = sL;

    if (L <= -1e29f) {
        if (tid == 0) { g_rowloss[i] = 0.f; g_rowflag[i] = 0; }
        return;
    }
    if (P == 0) {
        if (tid == 0) {
            g_rowloss[i] = softplus_fast(L - 10.f);
            g_rowflag[i] = 0;
        }
        return;
    }

    const __half* __restrict__ row = g_S + (size_t)i * N;
    const uint4* __restrict__ rv = reinterpret_cast<const uint4*>(row);

    float psum = 0.f;
    const int v0 = lo >> 3;
    const int v1 = (hi + 7) >> 3;
    for (int v = v0 + tid; v < v1; v += 256) {
        uint4 w = rv[v];
        const int j0 = v << 3;
        float s[8];
        {
            float2 f;
            f = __half22float2(*reinterpret_cast<__half2*>(&w.x)); s[0] = f.x; s[1] = f.y;
            f = __half22float2(*reinterpret_cast<__half2*>(&w.y)); s[2] = f.x; s[3] = f.y;
            f = __half22float2(*reinterpret_cast<__half2*>(&w.z)); s[4] = f.x; s[5] = f.y;
            f = __half22float2(*reinterpret_cast<__half2*>(&w.w)); s[6] = f.x; s[7] = f.y;
        }
        const bool interior = (j0 >= lo) && (j0 + 8 <= hi) &&
                              ((i < j0) || (i >= j0 + 8));
        if (interior) {
#pragma unroll
            for (int k = 0; k < 8; k++)
                psum += softplus_fast(L - s[k]);
        } else {
#pragma unroll
            for (int k = 0; k < 8; k++) {
                const int j = j0 + k;
                const bool m = (j >= lo) && (j < hi) && (j != i);
                psum += m ? softplus_fast(L - s[k]) : 0.f;
            }
        }
    }
    psum = wred_f(psum);
    if ((tid & 31) == 0) redf[tid >> 5] = psum;
    __syncthreads();
    if (tid == 0) {
        float tt = 0.f;
#pragma unroll
        for (int w = 0; w < 8; w++) tt += redf[w];
        g_rowloss[i] = tt / (float)P;
        g_rowflag[i] = 1;
    }
}

// ---------------- kernel 4: final deterministic reduction -------------------
__global__ void __launch_bounds__(256) k_finalize(float* __restrict__ out, int N)
{
    const int tid = threadIdx.x;
    const float4* rl = reinterpret_cast<const float4*>(g_rowloss);
    const int4*   fl = reinterpret_cast<const int4*>(g_rowflag);
    float s = 0.f;
    int c = 0;
    for (int v = tid; v < N / 4; v += 256) {
        float4 a = rl[v];
        int4   b = fl[v];
        s += a.x + a.y + a.z + a.w;
        c += b.x + b.y + b.z + b.w;
    }
    s = wred_f(s);
    c = wred_i(c);
    __shared__ float redf[8];
    __shared__ int   redi[8];
    if ((tid & 31) == 0) { redf[tid >> 5] = s; redi[tid >> 5] = c; }
    __syncthreads();
    if (tid == 0) {
        float tt = 0.f; int p = 0;
#pragma unroll
        for (int w = 0; w < 8; w++) { tt += redf[w]; p += redi[w]; }
        out[0] = tt / (float)(1 + p);
    }
}

// ---------------- launcher ---------------------------------------------------
extern "C" void kernel_launch(void* const* d_in, const int* in_sizes, int n_in,
                              void* d_out, int out_size)
{
    const float* feats  = (const float*)d_in[0];
    const int*   labels = (const int*)d_in[1];
    const int*   bad    = (const int*)d_in[2];
    float* out = (float*)d_out;

    const int N = in_sizes[1];            // 8192
    const int D = in_sizes[0] / N;        // 512

    cudaFuncSetAttribute(k_gemm_f16, cudaFuncAttributeMaxDynamicSharedMemorySize, SM_DYN);

    k_perm<<<1, 1024>>>(labels, bad, N);
    k_normalize<<<N, 128>>>(feats, N, D);

    const int ntiles = (NTILE * (NTILE + 1)) / 2;   // 2080 (most exit early)
    k_gemm_f16<<<ntiles, TCB, SM_DYN>>>(N, D);

    k_rowloss<<<N, 256>>>(N);
    k_finalize<<<1, 256>>>(out, N);
}

// round 11
// speedup vs baseline: 1.3522x; 1.1471x over previous
#include <cuda_runtime.h>
#include <cuda_fp16.h>
#include <math.h>
#include <stdint.h>

// Shapes fixed by the problem: N=8192, D=512, 3 classes
#define NMAX 8192
#define DMAX 512
#define NTILE 64   // N / 128

// ---------------- device scratch (static, no runtime allocation) ------------
__device__ __half g_fh[(size_t)NMAX * DMAX];   // permuted normalized features (8 MB)
__device__ __half g_S[(size_t)NMAX * NMAX];    // scaled logits, fp16 (class tiles only)
__device__ float  g_negpart[(size_t)NMAX * 64];// per-(row, col-tile) exp partials (2 MB)
__device__ int    g_perm[NMAX];
__device__ int    g_bnd[4];                    // {0, b1, b2, NV}
__device__ float  g_rowloss[NMAX];
__device__ int    g_rowflag[NMAX];

// ---------------- helpers ----------------------------------------------------
__device__ __forceinline__ float wred_f(float x) {
#pragma unroll
    for (int o = 16; o; o >>= 1) x += __shfl_xor_sync(0xffffffffu, x, o);
    return x;
}
__device__ __forceinline__ int wred_i(int x) {
#pragma unroll
    for (int o = 16; o; o >>= 1) x += __shfl_xor_sync(0xffffffffu, x, o);
    return x;
}
__device__ __forceinline__ float softplus_fast(float d) {
    return fmaxf(d, 0.f) + __logf(1.f + __expf(-fabsf(d)));
}
__device__ __forceinline__ int clsof(int x, int b1, int b2, int NV) {
    return (x < b1) ? 0 : (x < b2) ? 1 : (x < NV) ? 2 : 3;
}

__device__ __forceinline__ void mma_f16(float* d, const uint32_t* a, const uint32_t* b) {
    asm volatile(
        "mma.sync.aligned.m16n8k16.row.col.f32.f16.f16.f32 "
        "{%0,%1,%2,%3}, {%4,%5,%6,%7}, {%8,%9}, {%0,%1,%2,%3};"
        : "+f"(d[0]), "+f"(d[1]), "+f"(d[2]), "+f"(d[3])
        : "r"(a[0]), "r"(a[1]), "r"(a[2]), "r"(a[3]),
          "r"(b[0]), "r"(b[1]));
}
__device__ __forceinline__ void ldsm_x4(uint32_t* r, uint32_t a) {
    asm volatile("ldmatrix.sync.aligned.m8n8.x4.shared.b16 {%0,%1,%2,%3}, [%4];"
                 : "=r"(r[0]), "=r"(r[1]), "=r"(r[2]), "=r"(r[3]) : "r"(a));
}
__device__ __forceinline__ void ldsm_x2(uint32_t* r, uint32_t a) {
    asm volatile("ldmatrix.sync.aligned.m8n8.x2.shared.b16 {%0,%1}, [%2];"
                 : "=r"(r[0]), "=r"(r[1]) : "r"(a));
}
__device__ __forceinline__ void cp_async16(uint32_t dst, const void* src) {
    size_t g = __cvta_generic_to_global(src);
    asm volatile("cp.async.cg.shared.global [%0], [%1], 16;"
                 :: "r"(dst), "l"(g) : "memory");
}

// ---------------- kernel 0: stable counting sort (1 block, warp scans) ------
__global__ void __launch_bounds__(1024) k_perm(
    const int* __restrict__ labels,
    const int* __restrict__ bad,
    int N)
{
    __shared__ uint32_t wt01[32], wt23[32];
    const int t = threadIdx.x;
    const int lane = t & 31;
    const int wid = t >> 5;

    const int4* lab4 = reinterpret_cast<const int4*>(labels);
    const int4* bad4 = reinterpret_cast<const int4*>(bad);
    int4 l0 = lab4[t * 2], l1 = lab4[t * 2 + 1];
    int4 d0 = bad4[t * 2], d1 = bad4[t * 2 + 1];

    int code[8];
    code[0] = (d0.x == 0) ? l0.x : 3;
    code[1] = (d0.y == 0) ? l0.y : 3;
    code[2] = (d0.z == 0) ? l0.z : 3;
    code[3] = (d0.w == 0) ? l0.w : 3;
    code[4] = (d1.x == 0) ? l1.x : 3;
    code[5] = (d1.y == 0) ? l1.y : 3;
    code[6] = (d1.z == 0) ? l1.z : 3;
    code[7] = (d1.w == 0) ? l1.w : 3;

    int cnt[4] = {0, 0, 0, 0};
#pragma unroll
    for (int e = 0; e < 8; e++) cnt[code[e]]++;

    uint32_t v01 = (uint32_t)cnt[0] | ((uint32_t)cnt[1] << 16);
    uint32_t v23 = (uint32_t)cnt[2] | ((uint32_t)cnt[3] << 16);
    uint32_t s01 = v01, s23 = v23;
#pragma unroll
    for (int off = 1; off < 32; off <<= 1) {
        uint32_t t1 = __shfl_up_sync(0xffffffffu, s01, off);
        uint32_t t2 = __shfl_up_sync(0xffffffffu, s23, off);
        if (lane >= off) { s01 += t1; s23 += t2; }
    }
    if (lane == 31) { wt01[wid] = s01; wt23[wid] = s23; }
    __syncthreads();
    if (wid == 0) {
        uint32_t w1 = wt01[lane], w2 = wt23[lane];
#pragma unroll
        for (int off = 1; off < 32; off <<= 1) {
            uint32_t t1 = __shfl_up_sync(0xffffffffu, w1, off);
            uint32_t t2 = __shfl_up_sync(0xffffffffu, w2, off);
            if (lane >= off) { w1 += t1; w2 += t2; }
        }
        wt01[lane] = w1; wt23[lane] = w2;
    }
    __syncthreads();

    const uint32_t wp01 = wid ? wt01[wid - 1] : 0u;
    const uint32_t wp23 = wid ? wt23[wid - 1] : 0u;
    const uint32_t tt01 = wt01[31], tt23 = wt23[31];

    const uint32_t ep01 = wp01 + s01 - v01;
    const uint32_t ep23 = wp23 + s23 - v23;
    int pre[4] = { (int)(ep01 & 0xffffu), (int)(ep01 >> 16),
                   (int)(ep23 & 0xffffu), (int)(ep23 >> 16) };
    const int tot0 = (int)(tt01 & 0xffffu);
    const int tot1 = (int)(tt01 >> 16);
    const int tot2 = (int)(tt23 & 0xffffu);
    int base[4] = { 0, tot0, tot0 + tot1, tot0 + tot1 + tot2 };

    int r[4] = {0, 0, 0, 0};
#pragma unroll
    for (int e = 0; e < 8; e++) {
        const int j = t * 8 + e;
        const int c = code[e];
        g_perm[base[c] + pre[c] + r[c]] = j;
        r[c]++;
    }
    if (t == 0) {
        g_bnd[0] = 0;
        g_bnd[1] = base[1];
        g_bnd[2] = base[2];
        g_bnd[3] = base[3];
    }
}

// ---------------- kernel 1: normalize + gather-permute -> fp16 --------------
__global__ void __launch_bounds__(128) k_normalize(
    const float* __restrict__ feats, int N, int D)
{
    const int i = blockIdx.x;
    const int tid = threadIdx.x;
    const int src = g_perm[i];
    float4 v = reinterpret_cast<const float4*>(feats + (size_t)src * D)[tid];
    float ss = v.x * v.x + v.y * v.y + v.z * v.z + v.w * v.w;
    ss = wred_f(ss);
    __shared__ float w[4];
    if ((tid & 31) == 0) w[tid >> 5] = ss;
    __syncthreads();
    float rinv = rsqrtf(w[0] + w[1] + w[2] + w[3]);
    uint2 o;
    __half2 h0 = __floats2half2_rn(v.x * rinv, v.y * rinv);
    __half2 h1 = __floats2half2_rn(v.z * rinv, v.w * rinv);
    o.x = *reinterpret_cast<uint32_t*>(&h0);
    o.y = *reinterpret_cast<uint32_t*>(&h1);
    reinterpret_cast<uint2*>(g_fh + (size_t)i * D)[tid] = o;
}

// ---------------- kernel 2: fp16 GEMM (cp.async + ldmatrix) + partials ------
#define TCB 256
#define SM_A0 0
#define SM_A1 16384
#define SM_B0 32768
#define SM_B1 49152
#define SM_DYN 65536

__global__ void __launch_bounds__(TCB, 2) k_gemm_f16(int N, int D)
{
    extern __shared__ __align__(16) unsigned char dsm[];
    const uint32_t sbase = (uint32_t)__cvta_generic_to_shared(dsm);

    // linear block id -> upper-triangle (by, bx), bx >= by
    int t = blockIdx.x;
    int by = 0;
    {
        int rem = t;
        while (rem >= NTILE - by) { rem -= NTILE - by; by++; }
        t = rem;
    }
    const int bx = by + t;

    const int b1 = g_bnd[1];
    const int b2 = g_bnd[2];
    const int NV = g_bnd[3];
    const int ntv = (NV + 127) >> 7;
    if (bx >= ntv) return;

    const int row0 = by * 128;
    const int col0 = bx * 128;

    const int tid  = threadIdx.x;
    const int lane = tid & 31;
    const int warp = tid >> 5;
    const int wm   = warp >> 2;       // 0..1 (64 rows each)
    const int wn   = warp & 3;        // 0..3 (32 cols each)

    const __half* __restrict__ fA = g_fh + (size_t)row0 * D;
    const __half* __restrict__ fB = g_fh + (size_t)col0 * D;

    const uint32_t aB[2] = {sbase + SM_A0, sbase + SM_A1};
    const uint32_t bB[2] = {sbase + SM_B0, sbase + SM_B1};

    int cp_r[4], cp_sw[4];
#pragma unroll
    for (int i = 0; i < 4; i++) {
        const int e = tid + i * TCB;       // 0..1023
        const int r = e >> 3, g = e & 7;
        cp_r[i]  = r;
        cp_sw[i] = r * 128 + ((g * 16) ^ ((r & 7) << 4));
    }

    float acc[4][4][4];
#pragma unroll
    for (int a = 0; a < 4; a++)
#pragma unroll
        for (int b = 0; b < 4; b++)
#pragma unroll
            for (int c = 0; c < 4; c++) acc[a][b][c] = 0.f;

    const int rr = lane & 7;
    const int xr = rr << 4;
    const int qa = lane >> 3;
    const int kA = (qa >> 1) << 4;
    const int kB = ((lane >> 3) & 1) << 4;
    int rowA[4], rowB[4];
#pragma unroll
    for (int mt = 0; mt < 4; mt++)
        rowA[mt] = ((wm << 6) + (mt << 4) + ((qa & 1) << 3) + rr) * 128;
#pragma unroll
    for (int nt = 0; nt < 4; nt++)
        rowB[nt] = ((wn << 5) + (nt << 3) + rr) * 128;

    const int NCH = D >> 6;

    {
#pragma unroll
        for (int i = 0; i < 4; i++) {
            cp_async16(aB[0] + cp_sw[i], fA + (size_t)cp_r[i] * D + ((tid + i * TCB) & 7) * 8);
            cp_async16(bB[0] + cp_sw[i], fB + (size_t)cp_r[i] * D + ((tid + i * TCB) & 7) * 8);
        }
        asm volatile("cp.async.commit_group;" ::: "memory");
    }

    for (int c = 0; c < NCH; c++) {
        const int buf = c & 1;
        if (c + 1 < NCH) {
            const int koff = (c + 1) << 6;
            const int nb = (c + 1) & 1;
#pragma unroll
            for (int i = 0; i < 4; i++) {
                cp_async16(aB[nb] + cp_sw[i], fA + (size_t)cp_r[i] * D + koff + ((tid + i * TCB) & 7) * 8);
                cp_async16(bB[nb] + cp_sw[i], fB + (size_t)cp_r[i] * D + koff + ((tid + i * TCB) & 7) * 8);
            }
            asm volatile("cp.async.commit_group;" ::: "memory");
            asm volatile("cp.async.wait_group 1;" ::: "memory");
        } else {
            asm volatile("cp.async.wait_group 0;" ::: "memory");
        }
        __syncthreads();

        const uint32_t ab = aB[buf];
        const uint32_t bb = bB[buf];
#pragma unroll
        for (int ks = 0; ks < 4; ks++) {
            const int kk = ks << 5;
            uint32_t Af[4][4], Bf[4][2];
#pragma unroll
            for (int mt = 0; mt < 4; mt++)
                ldsm_x4(Af[mt], ab + rowA[mt] + ((kk + kA) ^ xr));
#pragma unroll
            for (int nt = 0; nt < 4; nt++)
                ldsm_x2(Bf[nt], bb + rowB[nt] + ((kk + kB) ^ xr));
#pragma unroll
            for (int mt = 0; mt < 4; mt++)
#pragma unroll
                for (int nt = 0; nt < 4; nt++)
                    mma_f16(acc[mt][nt], Af[mt], Bf[nt]);
        }
        __syncthreads();
    }

    // ---- epilogue ----
    float* SRow = reinterpret_cast<float*>(dsm);           // [128][4]
    float* SCol = reinterpret_cast<float*>(dsm + 2048);    // [128][2]
    __half* Tsm = reinterpret_cast<__half*>(dsm);          // reuse

    const float invT = 10.f;
    const int g  = lane >> 2;
    const int tq = lane & 3;

    bool storeT;
    {
        const int r0 = row0, r1 = row0 + 128, c0 = col0, c1 = col0 + 128;
        storeT = (r0 < b1 && c0 < b1)
              || (r0 < b2 && r1 > b1 && c0 < b2 && c1 > b1)
              || (r1 > b2 && c1 > b2 && row0 < NV && col0 < NV);
    }
    const bool allsame =
        (clsof(row0, b1, b2, NV) == clsof(row0 + 127, b1, b2, NV)) &&
        (clsof(col0, b1, b2, NV) == clsof(col0 + 127, b1, b2, NV)) &&
        (clsof(row0, b1, b2, NV) == clsof(col0, b1, b2, NV)) &&
        (clsof(row0, b1, b2, NV) != 3);

    if (storeT) {
        __half* __restrict__ S = g_S;
#pragma unroll
        for (int mt = 0; mt < 4; mt++) {
            const int row = row0 + (wm << 6) + (mt << 4) + g;
#pragma unroll
            for (int nt = 0; nt < 4; nt++) {
                const int col = col0 + (wn << 5) + (nt << 3) + (tq << 1);
                __half2 lo = __floats2half2_rn(acc[mt][nt][0] * invT, acc[mt][nt][1] * invT);
                __half2 hi = __floats2half2_rn(acc[mt][nt][2] * invT, acc[mt][nt][3] * invT);
                *reinterpret_cast<__half2*>(&S[(size_t)row * N + col]) = lo;
                *reinterpret_cast<__half2*>(&S[(size_t)(row + 8) * N + col]) = hi;
            }
        }
    }

    float rsum[8] = {0, 0, 0, 0, 0, 0, 0, 0};
    float csum[8] = {0, 0, 0, 0, 0, 0, 0, 0};
    if (!allsame) {
        int rcls[8], ccls[8];
#pragma unroll
        for (int mt = 0; mt < 4; mt++)
#pragma unroll
            for (int h = 0; h < 2; h++) {
                const int r = row0 + (wm << 6) + (mt << 4) + g + 8 * h;
                rcls[mt * 2 + h] = clsof(r, b1, b2, NV);
            }
#pragma unroll
        for (int nt = 0; nt < 4; nt++)
#pragma unroll
            for (int c = 0; c < 2; c++) {
                const int cc = col0 + (wn << 5) + (nt << 3) + (tq << 1) + c;
                ccls[nt * 2 + c] = clsof(cc, b1, b2, NV);
            }
#pragma unroll
        for (int mt = 0; mt < 4; mt++)
#pragma unroll
            for (int h = 0; h < 2; h++) {
                const int rc = rcls[mt * 2 + h];
#pragma unroll
                for (int nt = 0; nt < 4; nt++)
#pragma unroll
                    for (int c = 0; c < 2; c++) {
                        const int cc = ccls[nt * 2 + c];
                        const float s = acc[mt][nt][2 * h + c] * invT;
                        const float e = __expf(s - 10.f);
                        const bool m = (rc != cc) && (rc != 3) && (cc != 3);
                        const float ev = m ? e : 0.f;
                        rsum[mt * 2 + h] += ev;
                        csum[nt * 2 + c] += ev;
                    }
            }
#pragma unroll
        for (int k = 0; k < 8; k++) {
            rsum[k] += __shfl_xor_sync(0xffffffffu, rsum[k], 1);
            rsum[k] += __shfl_xor_sync(0xffffffffu, rsum[k], 2);
            csum[k] += __shfl_xor_sync(0xffffffffu, csum[k], 4);
            csum[k] += __shfl_xor_sync(0xffffffffu, csum[k], 8);
            csum[k] += __shfl_xor_sync(0xffffffffu, csum[k], 16);
        }
    }
    if (tq == 0) {
#pragma unroll
        for (int mt = 0; mt < 4; mt++)
#pragma unroll
            for (int h = 0; h < 2; h++) {
                const int rl = (wm << 6) + (mt << 4) + g + 8 * h;
                SRow[rl * 4 + wn] = rsum[mt * 2 + h];
            }
    }
    if (g == 0) {
#pragma unroll
        for (int nt = 0; nt < 4; nt++)
#pragma unroll
            for (int c = 0; c < 2; c++) {
                const int cl = (wn << 5) + (nt << 3) + (tq << 1) + c;
                SCol[cl * 2 + wm] = csum[nt * 2 + c];
            }
    }
    __syncthreads();

    if (tid < 128) {
        const float rp = SRow[tid * 4 + 0] + SRow[tid * 4 + 1]
                       + SRow[tid * 4 + 2] + SRow[tid * 4 + 3];
        g_negpart[(size_t)(row0 + tid) * 64 + bx] = rp;
    } else if (bx != by) {
        const int c = tid - 128;
        const float cp = SCol[c * 2 + 0] + SCol[c * 2 + 1];
        g_negpart[(size_t)(col0 + c) * 64 + by] = cp;
    }

    if (storeT && bx != by) {
        __syncthreads();
#pragma unroll
        for (int mt = 0; mt < 4; mt++) {
            const int r = (wm << 6) + (mt << 4) + g;
#pragma unroll
            for (int nt = 0; nt < 4; nt++) {
                const int c = (wn << 5) + (nt << 3) + (tq << 1);
                Tsm[(c) * 136 + r]         = __float2half_rn(acc[mt][nt][0] * invT);
                Tsm[(c + 1) * 136 + r]     = __float2half_rn(acc[mt][nt][1] * invT);
                Tsm[(c) * 136 + r + 8]     = __float2half_rn(acc[mt][nt][2] * invT);
                Tsm[(c + 1) * 136 + r + 8] = __float2half_rn(acc[mt][nt][3] * invT);
            }
        }
        __syncthreads();
        const int tr  = tid >> 1;
        const int seg = (tid & 1) << 6;
        const uint4* src = reinterpret_cast<const uint4*>(&Tsm[tr * 136 + seg]);
        uint4* dst = reinterpret_cast<uint4*>(&g_S[(size_t)(col0 + tr) * N + row0 + seg]);
#pragma unroll
        for (int k = 0; k < 8; k++) dst[k] = src[k];
    }
}

// ---------------- kernel 3: per-row loss, ONE WARP PER ROW ------------------
// 8 warps per block, grid N/8. No block syncs; wred_f broadcasts to all lanes.
__global__ void __launch_bounds__(256) k_rowloss(int N)
{
    const int tid  = threadIdx.x;
    const int lane = tid & 31;
    const int w    = tid >> 5;
    const int i    = blockIdx.x * 8 + w;

    const int b1 = g_bnd[1];
    const int b2 = g_bnd[2];
    const int NV = g_bnd[3];

    if (i >= NV) {
        if (lane == 0) { g_rowloss[i] = 0.f; g_rowflag[i] = 0; }
        return;
    }

    const int lo = (i < b1) ? 0  : ((i < b2) ? b1 : b2);
    const int hi = (i < b1) ? b1 : ((i < b2) ? b2 : NV);
    const int P  = hi - lo - 1;
    const int ntv = (NV + 127) >> 7;

    // negsum from tile partials (<=64 slots; fixed order)
    const float* __restrict__ np = g_negpart + (size_t)i * 64;
    float ns = (lane < ntv) ? np[lane] : 0.f;
    if (ntv > 32 && lane + 32 < ntv) ns += np[lane + 32];
    ns = wred_f(ns);                       // sum in ALL lanes
    const float L = (ns > 0.f) ? (__logf(ns) + 10.f) : -1e30f;

    if (L <= -1e29f) {
        if (lane == 0) { g_rowloss[i] = 0.f; g_rowflag[i] = 0; }
        return;
    }
    if (P == 0) {
        if (lane == 0) {
            g_rowloss[i] = softplus_fast(L - 10.f);
            g_rowflag[i] = 0;
        }
        return;
    }

    // psum over positives [lo, hi) \ {i}, 8-wide, interior fast path
    const uint4* __restrict__ rv = reinterpret_cast<const uint4*>(g_S + (size_t)i * N);

    float psum = 0.f;
    const int v0 = lo >> 3;
    const int v1 = (hi + 7) >> 3;
    for (int v = v0 + lane; v < v1; v += 32) {
        uint4 wv = rv[v];
        const int j0 = v << 3;
        float s[8];
        {
            float2 f;
            f = __half22float2(*reinterpret_cast<__half2*>(&wv.x)); s[0] = f.x; s[1] = f.y;
            f = __half22float2(*reinterpret_cast<__half2*>(&wv.y)); s[2] = f.x; s[3] = f.y;
            f = __half22float2(*reinterpret_cast<__half2*>(&wv.z)); s[4] = f.x; s[5] = f.y;
            f = __half22float2(*reinterpret_cast<__half2*>(&wv.w)); s[6] = f.x; s[7] = f.y;
        }
        const bool interior = (j0 >= lo) && (j0 + 8 <= hi) &&
                              ((i < j0) || (i >= j0 + 8));
        if (interior) {
#pragma unroll
            for (int k = 0; k < 8; k++)
                psum += softplus_fast(L - s[k]);
        } else {
#pragma unroll
            for (int k = 0; k < 8; k++) {
                const int j = j0 + k;
                const bool m = (j >= lo) && (j < hi) && (j != i);
                psum += m ? softplus_fast(L - s[k]) : 0.f;
            }
        }
    }
    psum = wred_f(psum);
    if (lane == 0) {
        g_rowloss[i] = psum / (float)P;
        g_rowflag[i] = 1;
    }
}

// ---------------- kernel 4: final deterministic reduction (1024 thr) --------
__global__ void __launch_bounds__(1024) k_finalize(float* __restrict__ out, int N)
{
    const int tid = threadIdx.x;
    const float4* rl = reinterpret_cast<const float4*>(g_rowloss);
    const int4*   fl = reinterpret_cast<const int4*>(g_rowflag);
    float s = 0.f;
    int c = 0;
    for (int v = tid; v < N / 4; v += 1024) {
        float4 a = rl[v];
        int4   b = fl[v];
        s += a.x + a.y + a.z + a.w;
        c += b.x + b.y + b.z + b.w;
    }
    s = wred_f(s);
    c = wred_i(c);
    __shared__ float redf[32];
    __shared__ int   redi[32];
    if ((tid & 31) == 0) { redf[tid >> 5] = s; redi[tid >> 5] = c; }
    __syncthreads();
    if (tid == 0) {
        float tt = 0.f; int p = 0;
#pragma unroll
        for (int w = 0; w < 32; w++) { tt += redf[w]; p += redi[w]; }
        out[0] = tt / (float)(1 + p);
    }
}

// ---------------- launcher ---------------------------------------------------
extern "C" void kernel_launch(void* const* d_in, const int* in_sizes, int n_in,
                              void* d_out, int out_size)
{
    const float* feats  = (const float*)d_in[0];
    const int*   labels = (const int*)d_in[1];
    const int*   bad    = (const int*)d_in[2];
    float* out = (float*)d_out;

    const int N = in_sizes[1];            // 8192
    const int D = in_sizes[0] / N;        // 512

    cudaFuncSetAttribute(k_gemm_f16, cudaFuncAttributeMaxDynamicSharedMemorySize, SM_DYN);

    k_perm<<<1, 1024>>>(labels, bad, N);
    k_normalize<<<N, 128>>>(feats, N, D);

    const int ntiles = (NTILE * (NTILE + 1)) / 2;   // 2080 (most exit early)
    k_gemm_f16<<<ntiles, TCB, SM_DYN>>>(N, D);

    k_rowloss<<<N / 8, 256>>>(N);
    k_finalize<<<1, 1024>>>(out, N);
}